// round 16
// baseline (speedup 1.0000x reference)
#include <cuda_runtime.h>
#include <cuda_bf16.h>
#include <cuda_fp16.h>
#include <cstdint>
#include <cstdio>

#define N_ENT 50000
#define N_USR 10000
#define NND   60000
#define NEDGE 1920000
#define NREL  16
#define BATCH 4096

typedef unsigned long long ull;

// packed f32x2 FMA: d.lo += a.lo*b.lo ; d.hi += a.hi*b.hi  (one issue slot, 2 FMAs)
#define FFMA2(d, a, b) asm("fma.rn.f32x2 %0, %1, %2, %0;" : "+l"(d) : "l"(a), "l"(b))

__device__ __forceinline__ float f2lo(ull v) { return __uint_as_float((unsigned)v); }
__device__ __forceinline__ float f2hi(ull v) { return __uint_as_float((unsigned)(v >> 32)); }
__device__ __forceinline__ float f2sum(ull v) { return f2lo(v) + f2hi(v); }
__device__ __forceinline__ float sigmoidf_(float g) { return 1.f / (1.f + __expf(-g)); }

// ---------------- scratch (device globals; zero-initialized; reset at END) -------
__device__ float  g_encoded[NND * 32];
__device__ __half g_ench[NND * 32];
__device__ float  g_x1[NND * 32];
__device__ __half g_x1h[NND * 32];
__device__ float  g_x2[NND * 16];
__device__ __align__(16) __half g_agg1h[NND * 32];
__device__ __align__(16) __half g_agg2h[NND * 32];
__device__ int    g_cnt[NND];
__device__ ull    g_epack[NEDGE];      // src | dst<<16 | rel<<32
__device__ float  g_gd[NND * 16];
__device__ float  g_gs[NND * 16];
__device__ float  g_wsum2[NREL * 64];
__device__ float  g_loss;

extern __shared__ unsigned char dynsmem[];

// ---------------- prep: pack + degree count + wsum2 (side stream) ----------------
__global__ void __launch_bounds__(256) prep_kernel(const int* __restrict__ esrc,
                                                   const int* __restrict__ edst,
                                                   const int* __restrict__ erel,
                                                   const float* __restrict__ Wr2) {
    if (blockIdx.x == gridDim.x - 1) {
        for (int i = threadIdx.x; i < NREL * 64; i += 256) {
            const float* p = Wr2 + i * 32;
            float s = 0.f;
#pragma unroll
            for (int t = 0; t < 32; t++) s += p[t];
            g_wsum2[i] = s;
        }
        return;
    }
    int e = blockIdx.x * blockDim.x + threadIdx.x;
    if (e < NEDGE) {
        int d = edst[e];
        g_epack[e] = (ull)(unsigned)esrc[e] | ((ull)(unsigned)d << 16)
                   | ((ull)(unsigned)erel[e] << 32);
        atomicAdd(&g_cnt[d], 1);
    }
}

// ---------------- encode v3 (proven): NB=4, fused gate-1 (inline wsum1) ----------
// smem: sW0 32K | sW1 16K | stg 16K | sG 4K = 68 KB
__global__ void __launch_bounds__(256, 3) encode_kernel(
    const float* __restrict__ ent, const float* __restrict__ usr,
    const float* __restrict__ W0, const float* __restrict__ b0,
    const float* __restrict__ W1, const float* __restrict__ b1,
    const float* __restrict__ Wr1) {
    float2* sW0 = (float2*)dynsmem;               // 32 k2 x 128 col
    float2* sW1 = sW0 + 32 * 128;                 // 64 k2 x 32 col
    float*  stg = (float*)(sW1 + 64 * 32);        // 8 warps x 512 floats
    float2* sG  = (float2*)(stg + 8 * 512);       // 16 k2 x 32 lanes

    for (int i = threadIdx.x; i < 32 * 128; i += 256) {
        int k2 = i >> 7, j = i & 127;
        sW0[i] = make_float2(W0[(2 * k2) * 128 + j], W0[(2 * k2 + 1) * 128 + j]);
    }
    for (int i = threadIdx.x; i < 64 * 32; i += 256) {
        int k2 = i >> 5, j = i & 31;
        sW1[i] = make_float2(W1[(2 * k2) * 32 + j], W1[(2 * k2 + 1) * 32 + j]);
    }
    // inline wsum1: sG[(k2,ln)] = (sum Wr1 row base+2k2, sum row base+2k2+1)
    for (int i = threadIdx.x; i < 16 * 32; i += 256) {
        int k2 = i >> 5, ln = i & 31;
        int base = (ln & 15) * 64 + ((ln >= 16) ? 32 : 0);
        const float* p0 = Wr1 + (base + 2 * k2) * 32;
        float s0 = 0.f, s1 = 0.f;
#pragma unroll
        for (int t = 0; t < 32; t++) { s0 += p0[t]; s1 += p0[32 + t]; }
        sG[i] = make_float2(s0, s1);
    }
    __syncthreads();

    const ull* sW0u = (const ull*)sW0;
    const ull* sW1u = (const ull*)sW1;
    const ull* sGu  = (const ull*)sG;
    const int lane  = threadIdx.x & 31;
    float* mystg    = stg + (threadIdx.x >> 5) * 512;
    ull*   mystgU   = (ull*)mystg;

    const int wid   = (blockIdx.x * 256 + threadIdx.x) >> 5;
    const int nwarp = (gridDim.x * 256) >> 5;
    const int rr    = lane & 15;

    float bb0[4];
#pragma unroll
    for (int p = 0; p < 4; p++) bb0[p] = b0[lane + 32 * p];
    const float bb1 = b1[lane];

    for (int g = wid; g < NND / 4; g += nwarp) {
#pragma unroll
        for (int m = 0; m < 4; m++) {
            int n = g * 4 + m;
            const float* e = (n < N_ENT) ? (ent + (size_t)n * 64)
                                         : (usr + (size_t)(n - N_ENT) * 64);
            ((float2*)mystg)[m * 32 + lane] = ((const float2*)e)[lane];
        }
        __syncwarp();

        ull acc[4][4];
#pragma unroll
        for (int m = 0; m < 4; m++)
#pragma unroll
            for (int p = 0; p < 4; p++) acc[m][p] = 0ull;
#pragma unroll 8
        for (int k2 = 0; k2 < 32; k2++) {
            ull w0 = sW0u[k2 * 128 + lane];
            ull w1 = sW0u[k2 * 128 + lane + 32];
            ull w2 = sW0u[k2 * 128 + lane + 64];
            ull w3 = sW0u[k2 * 128 + lane + 96];
#pragma unroll
            for (int m = 0; m < 4; m++) {
                ull b = mystgU[m * 32 + k2];
                FFMA2(acc[m][0], b, w0);
                FFMA2(acc[m][1], b, w1);
                FFMA2(acc[m][2], b, w2);
                FFMA2(acc[m][3], b, w3);
            }
        }
        __syncwarp();

#pragma unroll
        for (int m = 0; m < 4; m++)
#pragma unroll
            for (int p = 0; p < 4; p++)
                mystg[m * 128 + lane + 32 * p] = fmaxf(f2sum(acc[m][p]) + bb0[p], 0.f);
        __syncwarp();

        ull a2[4] = {0ull, 0ull, 0ull, 0ull};
#pragma unroll 8
        for (int k2 = 0; k2 < 64; k2++) {
            ull w = sW1u[k2 * 32 + lane];
#pragma unroll
            for (int m = 0; m < 4; m++) {
                ull b = mystgU[m * 64 + k2];
                FFMA2(a2[m], b, w);
            }
        }
        float vres[4];
#pragma unroll
        for (int m = 0; m < 4; m++) vres[m] = f2sum(a2[m]) + bb1;
        __syncwarp();
#pragma unroll
        for (int m = 0; m < 4; m++) {
            int node = g * 4 + m;
            g_encoded[(size_t)node * 32 + lane] = vres[m];
            g_ench[(size_t)node * 32 + lane]    = __float2half_rn(vres[m]);
            mystg[m * 32 + lane] = vres[m];
        }
        __syncwarp();

        ull ga[4] = {0ull, 0ull, 0ull, 0ull};
        const ulonglong2* mq = (const ulonglong2*)mystg;
#pragma unroll
        for (int k2p = 0; k2p < 8; k2p++) {
            ull w0 = sGu[(2 * k2p) * 32 + lane];
            ull w1 = sGu[(2 * k2p + 1) * 32 + lane];
#pragma unroll
            for (int m = 0; m < 4; m++) {
                ulonglong2 bb = mq[m * 8 + k2p];
                FFMA2(ga[m], bb.x, w0);
                FFMA2(ga[m], bb.y, w1);
            }
        }
#pragma unroll
        for (int m = 0; m < 4; m++) {
            int node = g * 4 + m;
            float gv = f2sum(ga[m]);
            if (lane < 16) g_gd[node * 16 + rr] = gv;
            else           g_gs[node * 16 + rr] = gv;
        }
        __syncwarp();
    }
}

// ---------------- decode ([32]->relu[128]->[64]) + sq-err loss (side stream) -----
__global__ void __launch_bounds__(256, 3) decode_kernel(
    const float* __restrict__ ent, const float* __restrict__ usr,
    const float* __restrict__ W0, const float* __restrict__ b0,
    const float* __restrict__ W1, const float* __restrict__ b1) {
    float2* sW0 = (float2*)dynsmem;
    float2* sW1 = sW0 + 16 * 128;
    float*  stg = (float*)(sW1 + 64 * 64);

    for (int i = threadIdx.x; i < 16 * 128; i += 256) {
        int k2 = i >> 7, j = i & 127;
        sW0[i] = make_float2(W0[(2 * k2) * 128 + j], W0[(2 * k2 + 1) * 128 + j]);
    }
    for (int i = threadIdx.x; i < 64 * 64; i += 256) {
        int k2 = i >> 6, j = i & 63;
        sW1[i] = make_float2(W1[(2 * k2) * 64 + j], W1[(2 * k2 + 1) * 64 + j]);
    }
    __syncthreads();

    const ull* sW0u = (const ull*)sW0;
    const ull* sW1u = (const ull*)sW1;
    const int lane  = threadIdx.x & 31;
    float* mystg    = stg + (threadIdx.x >> 5) * 512;
    ull*   mystgU   = (ull*)mystg;

    const int wid   = (blockIdx.x * 256 + threadIdx.x) >> 5;
    const int nwarp = (gridDim.x * 256) >> 5;

    float bb0[4];
#pragma unroll
    for (int p = 0; p < 4; p++) bb0[p] = b0[lane + 32 * p];
    const float bb1a = b1[lane], bb1b = b1[lane + 32];

    float lsum = 0.f;
    for (int g = wid; g < NND / 4; g += nwarp) {
#pragma unroll
        for (int m = 0; m < 4; m++)
            mystg[m * 32 + lane] = g_encoded[(size_t)(g * 4 + m) * 32 + lane];
        __syncwarp();

        ull acc[4][4];
#pragma unroll
        for (int m = 0; m < 4; m++)
#pragma unroll
            for (int p = 0; p < 4; p++) acc[m][p] = 0ull;
#pragma unroll
        for (int k2 = 0; k2 < 16; k2++) {
            ull w0 = sW0u[k2 * 128 + lane];
            ull w1 = sW0u[k2 * 128 + lane + 32];
            ull w2 = sW0u[k2 * 128 + lane + 64];
            ull w3 = sW0u[k2 * 128 + lane + 96];
#pragma unroll
            for (int m = 0; m < 4; m++) {
                ull b = mystgU[m * 16 + k2];
                FFMA2(acc[m][0], b, w0);
                FFMA2(acc[m][1], b, w1);
                FFMA2(acc[m][2], b, w2);
                FFMA2(acc[m][3], b, w3);
            }
        }
        __syncwarp();
#pragma unroll
        for (int m = 0; m < 4; m++)
#pragma unroll
            for (int p = 0; p < 4; p++)
                mystg[m * 128 + lane + 32 * p] = fmaxf(f2sum(acc[m][p]) + bb0[p], 0.f);
        __syncwarp();

        ull a0[4] = {0ull, 0ull, 0ull, 0ull};
        ull a1[4] = {0ull, 0ull, 0ull, 0ull};
#pragma unroll 8
        for (int k2 = 0; k2 < 64; k2++) {
            ull w0 = sW1u[k2 * 64 + lane];
            ull w1 = sW1u[k2 * 64 + lane + 32];
#pragma unroll
            for (int m = 0; m < 4; m++) {
                ull b = mystgU[m * 64 + k2];
                FFMA2(a0[m], b, w0);
                FFMA2(a1[m], b, w1);
            }
        }
#pragma unroll
        for (int m = 0; m < 4; m++) {
            int n = g * 4 + m;
            const float* e = (n < N_ENT) ? (ent + (size_t)n * 64)
                                         : (usr + (size_t)(n - N_ENT) * 64);
            float q0 = (f2sum(a0[m]) + bb1a) - e[lane];
            float q1 = (f2sum(a1[m]) + bb1b) - e[lane + 32];
            lsum += q0 * q0 + q1 * q1;
        }
        __syncwarp();
    }
#pragma unroll
    for (int o = 16; o; o >>= 1) lsum += __shfl_xor_sync(0xffffffffu, lsum, o);
    if (lane == 0) atomicAdd(&g_loss, lsum);
}

// ---------------- edge scatter: f16x2 reductions; layer-2 folds agg1 reset -------
template <int LAYER>
__global__ void __launch_bounds__(256) edge_kernel() {
    const __half* xh = (LAYER == 1) ? g_ench : g_x1h;
    __half* agg      = (LAYER == 1) ? g_agg1h : g_agg2h;

    if (LAYER == 2) {   // agg1h is dead after combine1; reset it here (coalesced)
        int t = blockIdx.x * 256 + threadIdx.x;
        if (t < NND * 16) ((unsigned*)g_agg1h)[t] = 0u;
    }

    const int lane = threadIdx.x & 31;
    const int g    = lane >> 2;
    const int sub  = lane & 3;
    const long long e8 = ((long long)(blockIdx.x * 256 + threadIdx.x) >> 5) * 8;

    float gate = 0.f; int s = 0, d = 0;
    if (lane < 8) {
        ull p = g_epack[e8 + lane];
        s = (int)(p & 0xFFFF);
        d = (int)((p >> 16) & 0xFFFF);
        int r = (int)(p >> 32);
        gate = sigmoidf_(g_gd[d * 16 + r] + g_gs[s * 16 + r]);
    }
    gate = __shfl_sync(0xffffffffu, gate, g);
    s    = __shfl_sync(0xffffffffu, s, g);
    d    = __shfl_sync(0xffffffffu, d, g);

    const uint4 raw = *reinterpret_cast<const uint4*>(xh + (size_t)s * 32 + sub * 8);
    __half2 g2 = __float2half2_rn(gate);
    __half2 h0 = __hmul2(*reinterpret_cast<const __half2*>(&raw.x), g2);
    __half2 h1 = __hmul2(*reinterpret_cast<const __half2*>(&raw.y), g2);
    __half2 h2 = __hmul2(*reinterpret_cast<const __half2*>(&raw.z), g2);
    __half2 h3 = __hmul2(*reinterpret_cast<const __half2*>(&raw.w), g2);

    __half* a = agg + (size_t)d * 32 + sub * 8;
    asm volatile("red.global.add.noftz.v4.f16x2 [%0], {%1, %2, %3, %4};"
                 :: "l"(a),
                    "r"(*reinterpret_cast<unsigned*>(&h0)),
                    "r"(*reinterpret_cast<unsigned*>(&h1)),
                    "r"(*reinterpret_cast<unsigned*>(&h2)),
                    "r"(*reinterpret_cast<unsigned*>(&h3))
                 : "memory");
}

// ---------------- combine v4 (proven): vectorized LDS, k-outer gate --------------
template <int LAYER>
__global__ void __launch_bounds__(256) combine_kernel(const float* __restrict__ linW,
                                                      const float* __restrict__ linb) {
    constexpr int OUT = (LAYER == 1) ? 32 : 16;
    const float* x    = (LAYER == 1) ? g_encoded : g_x1;
    const __half* agg = (LAYER == 1) ? g_agg1h : g_agg2h;
    float* xo         = (LAYER == 1) ? g_x1 : g_x2;

    __shared__ float2 sW[32 * OUT];
    __shared__ float2 sG[16 * 32];
    __shared__ __align__(16) float stg[8][256];

    for (int i = threadIdx.x; i < 32 * OUT; i += 256) {
        int k2 = i / OUT, j = i % OUT;
        sW[i] = make_float2(linW[(2 * k2) * OUT + j], linW[(2 * k2 + 1) * OUT + j]);
    }
    if (LAYER == 1) {
        for (int i = threadIdx.x; i < 16 * 32; i += 256) {
            int k2 = i >> 5, ln = i & 31;
            int base = (ln & 15) * 64 + ((ln >= 16) ? 32 : 0);
            sG[i] = make_float2(g_wsum2[base + 2 * k2], g_wsum2[base + 2 * k2 + 1]);
        }
    }
    __syncthreads();

    const ull* sWu = (const ull*)sW;
    const ull* sGu = (const ull*)sG;
    const int lane = threadIdx.x & 31;
    const int warp = threadIdx.x >> 5;
    float* mystg   = stg[warp];

    const int g = blockIdx.x * 8 + warp;       // grid = NND/32 = 1875, exact
    const int j = lane & (OUT - 1);

#pragma unroll
    for (int m = 0; m < 4; m++) {
        int node = g * 4 + m;
        float xv = x[(size_t)node * 32 + lane];
        int   c  = g_cnt[node];
        float av = (c > 0) ? __half2float(agg[(size_t)node * 32 + lane]) / (float)c : 0.f;
        mystg[m * 64 + lane]      = xv;
        mystg[m * 64 + 32 + lane] = av;
    }
    __syncwarp();

    ull acc[4] = {0ull, 0ull, 0ull, 0ull};
    const ulonglong2* mq = (const ulonglong2*)mystg;
#pragma unroll 8
    for (int k2p = 0; k2p < 16; k2p++) {
        ull w0 = sWu[(2 * k2p) * OUT + j];
        ull w1 = sWu[(2 * k2p + 1) * OUT + j];
#pragma unroll
        for (int m = 0; m < 4; m++) {
            ulonglong2 bb = mq[m * 16 + k2p];
            FFMA2(acc[m], bb.x, w0);
            FFMA2(acc[m], bb.y, w1);
        }
    }
    float bias = linb[j];
    float res[4];
#pragma unroll
    for (int m = 0; m < 4; m++) {
        float a = f2sum(acc[m]) + bias;
        res[m] = (a > 0.f) ? a : 0.01f * a;
    }
#pragma unroll
    for (int m = 0; m < 4; m++)
        if (lane < OUT) xo[(size_t)(g * 4 + m) * OUT + lane] = res[m];

    if (LAYER == 1) {
        __syncwarp();
#pragma unroll
        for (int m = 0; m < 4; m++) {
            int node = g * 4 + m;
            g_x1h[(size_t)node * 32 + lane] = __float2half_rn(res[m]);
            mystg[m * 32 + lane] = res[m];
        }
        __syncwarp();
        int rr = lane & 15;
        ull ga[4] = {0ull, 0ull, 0ull, 0ull};
#pragma unroll
        for (int k2p = 0; k2p < 8; k2p++) {
            ull w0 = sGu[(2 * k2p) * 32 + lane];
            ull w1 = sGu[(2 * k2p + 1) * 32 + lane];
#pragma unroll
            for (int m = 0; m < 4; m++) {
                ulonglong2 bb = mq[m * 8 + k2p];
                FFMA2(ga[m], bb.x, w0);
                FFMA2(ga[m], bb.y, w1);
            }
        }
#pragma unroll
        for (int m = 0; m < 4; m++) {
            int node = g * 4 + m;
            float gv = f2sum(ga[m]);
            if (lane < 16) g_gd[node * 16 + rr] = gv;
            else           g_gs[node * 16 + rr] = gv;
        }
    }
}

// ---------------- scoring + finalize + tail resets (one kernel) ------------------
__global__ void __launch_bounds__(256) score_finalize_kernel(
    const int* __restrict__ users, const int* __restrict__ items,
    float* __restrict__ out, int out_size) {
    int i  = blockIdx.x * blockDim.x + threadIdx.x;
    int st = gridDim.x * blockDim.x;
    if (i == 0) {
        if (out_size > BATCH) out[BATCH] = g_loss * (1.0f / (float)(NND * 64));
        g_loss = 0.f;
    }
    // tail resets (agg2h + cnt dead after combine2)
    unsigned* p = (unsigned*)g_agg2h;
    for (int k = i; k < NND * 16; k += st) p[k] = 0u;
    for (int k = i; k < NND; k += st) g_cnt[k] = 0;

    int wid = i >> 5;
    if (wid >= BATCH) return;
    int lane = threadIdx.x & 31;
    int un = N_ENT + users[wid];
    int it = items[wid];
    float s = g_x1[(size_t)un * 32 + lane] * g_x1[(size_t)it * 32 + lane];
    if (lane < 16) s += g_x2[(size_t)un * 16 + lane] * g_x2[(size_t)it * 16 + lane];
#pragma unroll
    for (int o = 16; o; o >>= 1) s += __shfl_xor_sync(0xffffffffu, s, o);
    if (lane == 0) out[wid] = s;
}

// ---------------- host launcher (fork/join; capture-legal) -----------------------
extern "C" void kernel_launch(void* const* d_in, const int* in_sizes, int n_in,
                              void* d_out, int out_size) {
    int iu = 0, ii = 1, ies = 2, ied = 3, ier = 4, ient = 5, iusr = 6;
    int ie0 = 7, ib0 = 8, ie1 = 9, ib1 = 10, id0 = 11, idb0 = 12, id1 = 13, idb1 = 14;
    int iWr1 = 15, ilW1 = 16, ilb1 = 17, iWr2 = 18, ilW2 = 19, ilb2 = 20;
    bool dict_order = (n_in >= 21 && in_sizes[0] == BATCH && in_sizes[2] == NEDGE &&
                       in_sizes[5] == N_ENT * 64);
    if (!dict_order) {
        ient = 0; iusr = 1; ie0 = 2; ib0 = 3; ie1 = 4; ib1 = 5;
        id0 = 6; idb0 = 7; id1 = 8; idb1 = 9;
        iWr1 = 10; ilW1 = 11; ilb1 = 12; iWr2 = 13; ilW2 = 14; ilb2 = 15;
        iu = 16; ii = 17; ies = 18; ied = 19; ier = 20;
    }
    const int* users = (const int*)d_in[iu];
    const int* items = (const int*)d_in[ii];
    const int* esrc  = (const int*)d_in[ies];
    const int* edst  = (const int*)d_in[ied];
    const int* erel  = (const int*)d_in[ier];
    const float* ent = (const float*)d_in[ient];
    const float* usr = (const float*)d_in[iusr];
    float* out = (float*)d_out;

    static cudaStream_t sPrep = nullptr, sDec = nullptr;
    static cudaEvent_t  eRoot = nullptr, ePrep = nullptr, eEnc = nullptr, eDec = nullptr;
    if (!sPrep) {
        cudaStreamCreateWithFlags(&sPrep, cudaStreamNonBlocking);
        cudaStreamCreateWithFlags(&sDec, cudaStreamNonBlocking);
        cudaEventCreateWithFlags(&eRoot, cudaEventDisableTiming);
        cudaEventCreateWithFlags(&ePrep, cudaEventDisableTiming);
        cudaEventCreateWithFlags(&eEnc,  cudaEventDisableTiming);
        cudaEventCreateWithFlags(&eDec,  cudaEventDisableTiming);
        cudaFuncSetAttribute(encode_kernel, cudaFuncAttributeMaxDynamicSharedMemorySize, 69632);
        cudaFuncSetAttribute(decode_kernel, cudaFuncAttributeMaxDynamicSharedMemorySize, 65536);
    }

    cudaEventRecord(eRoot, 0);

    // side: pack + count + wsum2, overlapped with encode
    cudaStreamWaitEvent(sPrep, eRoot, 0);
    prep_kernel<<<(NEDGE + 255) / 256 + 1, 256, 0, sPrep>>>(esrc, edst, erel,
                                (const float*)d_in[iWr2]);
    cudaEventRecord(ePrep, sPrep);

    // main: encode (inline wsum1, fused gate-1, fp16 mirror)
    encode_kernel<<<444, 256, 69632>>>(ent, usr,
                                (const float*)d_in[ie0], (const float*)d_in[ib0],
                                (const float*)d_in[ie1], (const float*)d_in[ib1],
                                (const float*)d_in[iWr1]);
    cudaEventRecord(eEnc, 0);

    // edge layer 1 — after prep joins
    cudaStreamWaitEvent(0, ePrep, 0);
    edge_kernel<1><<<NEDGE / 64, 256>>>();

    // side: decode/loss overlapped with edge1/combine1/edge2
    cudaStreamWaitEvent(sDec, eEnc, 0);
    decode_kernel<<<444, 256, 65536, sDec>>>(ent, usr,
                                (const float*)d_in[id0], (const float*)d_in[idb0],
                                (const float*)d_in[id1], (const float*)d_in[idb1]);
    cudaEventRecord(eDec, sDec);

    // combine 1 (+ fused gate-2, fp16 mirror)
    combine_kernel<1><<<NND / 32, 256>>>((const float*)d_in[ilW1],
                                         (const float*)d_in[ilb1]);
    // layer 2 (edge2 also resets agg1h)
    edge_kernel<2><<<NEDGE / 64, 256>>>();
    combine_kernel<2><<<NND / 32, 256>>>((const float*)d_in[ilW2],
                                         (const float*)d_in[ilb2]);

    // scoring + finalize + tail resets (joins decode)
    cudaStreamWaitEvent(0, eDec, 0);
    score_finalize_kernel<<<(BATCH * 32 + 255) / 256, 256>>>(users, items, out, out_size);
}

// round 17
// speedup vs baseline: 1.2908x; 1.2908x over previous
#include <cuda_runtime.h>
#include <cuda_bf16.h>
#include <cuda_fp16.h>
#include <cstdint>
#include <cstdio>

#define N_ENT 50000
#define N_USR 10000
#define NND   60000
#define NEDGE 1920000
#define NREL  16
#define BATCH 4096

typedef unsigned long long ull;

// packed f32x2 FMA: d.lo += a.lo*b.lo ; d.hi += a.hi*b.hi  (one issue slot, 2 FMAs)
#define FFMA2(d, a, b) asm("fma.rn.f32x2 %0, %1, %2, %0;" : "+l"(d) : "l"(a), "l"(b))

__device__ __forceinline__ float f2lo(ull v) { return __uint_as_float((unsigned)v); }
__device__ __forceinline__ float f2hi(ull v) { return __uint_as_float((unsigned)(v >> 32)); }
__device__ __forceinline__ float f2sum(ull v) { return f2lo(v) + f2hi(v); }
__device__ __forceinline__ float sigmoidf_(float g) { return 1.f / (1.f + __expf(-g)); }
__device__ __forceinline__ ull packf2(float lo, float hi) {
    return (ull)__float_as_uint(lo) | ((ull)__float_as_uint(hi) << 32);
}

// ---------------- scratch (device globals; zero-initialized; reset at END) -------
__device__ float  g_encoded[NND * 32];
__device__ __half g_ench[NND * 32];
__device__ float  g_x1[NND * 32];
__device__ __half g_x1h[NND * 32];
__device__ float  g_x2[NND * 16];
__device__ __align__(16) __half g_agg1h[NND * 32];
__device__ __align__(16) __half g_agg2h[NND * 32];
__device__ int    g_cnt[NND];
__device__ ull    g_epack[NEDGE];      // src | dst<<16 | rel<<32
__device__ float  g_gd[NND * 16];
__device__ float  g_gs[NND * 16];
__device__ float  g_wsum1[NREL * 64];
__device__ float  g_wsum2[NREL * 64];
__device__ float  g_loss;

extern __shared__ unsigned char dynsmem[];

// ---------------- wsum split (dedicated kernels; cheap) --------------------------
__global__ void __launch_bounds__(256) wsum_a_kernel(const float* __restrict__ Wr1) {
    int i = blockIdx.x * blockDim.x + threadIdx.x;
    if (i >= NREL * 64) return;
    const float* p = Wr1 + i * 32;
    float s = 0.f;
#pragma unroll
    for (int t = 0; t < 32; t++) s += p[t];
    g_wsum1[i] = s;
}
__global__ void __launch_bounds__(256) wsum_b_kernel(const float* __restrict__ Wr2) {
    int i = blockIdx.x * blockDim.x + threadIdx.x;
    if (i >= NREL * 64) return;
    const float* p = Wr2 + i * 32;
    float s = 0.f;
#pragma unroll
    for (int t = 0; t < 32; t++) s += p[t];
    g_wsum2[i] = s;
}

// ---------------- prep: pack edges + degree count (side stream, || encode) -------
__global__ void __launch_bounds__(256) prep_kernel(const int* __restrict__ esrc,
                                                   const int* __restrict__ edst,
                                                   const int* __restrict__ erel) {
    int e = blockIdx.x * blockDim.x + threadIdx.x;
    if (e < NEDGE) {
        int d = edst[e];
        g_epack[e] = (ull)(unsigned)esrc[e] | ((ull)(unsigned)d << 16)
                   | ((ull)(unsigned)erel[e] << 32);
        atomicAdd(&g_cnt[d], 1);
    }
}

// ---------------- encode v4 (proven): NB=8 with p-split --------------------------
__global__ void __launch_bounds__(256, 2) encode_kernel(
    const float* __restrict__ ent, const float* __restrict__ usr,
    const float* __restrict__ W0, const float* __restrict__ b0,
    const float* __restrict__ W1, const float* __restrict__ b1) {
    float2* sW0  = (float2*)dynsmem;
    ull*    sW1p = (ull*)(sW0 + 32 * 128);
    float2* sG   = (float2*)(sW1p + 2048);
    float*  stg  = (float*)(sG + 512);

    for (int i = threadIdx.x; i < 32 * 128; i += 256) {
        int k2 = i >> 7, j = i & 127;
        sW0[i] = make_float2(W0[(2 * k2) * 128 + j], W0[(2 * k2 + 1) * 128 + j]);
    }
    for (int i = threadIdx.x; i < 64 * 32; i += 256) {
        int k2 = i >> 5, j = i & 31;
        sW1p[(k2 >> 1) * 64 + j * 2 + (k2 & 1)] =
            packf2(W1[(2 * k2) * 32 + j], W1[(2 * k2 + 1) * 32 + j]);
    }
    for (int i = threadIdx.x; i < 16 * 32; i += 256) {
        int k2 = i >> 5, ln = i & 31;
        int base = (ln & 15) * 64 + ((ln >= 16) ? 32 : 0);
        sG[i] = make_float2(g_wsum1[base + 2 * k2], g_wsum1[base + 2 * k2 + 1]);
    }
    __syncthreads();

    const ull*        sW0u = (const ull*)sW0;
    const ulonglong2* sW1q = (const ulonglong2*)sW1p;
    const ull*        sGu  = (const ull*)sG;
    const int lane = threadIdx.x & 31;
    float* mystg   = stg + (threadIdx.x >> 5) * 1536;
    float* myin    = mystg + 1024;
    const ulonglong2* mqH = (const ulonglong2*)mystg;
    const ulonglong2* mqI = (const ulonglong2*)myin;

    const int wid   = (blockIdx.x * 256 + threadIdx.x) >> 5;
    const int nwarp = (gridDim.x * 256) >> 5;
    const int rr    = lane & 15;

    float bb0[4];
#pragma unroll
    for (int p = 0; p < 4; p++) bb0[p] = b0[lane + 32 * p];
    const float bb1 = b1[lane];

    for (int g = wid; g < NND / 8; g += nwarp) {
#pragma unroll
        for (int m = 0; m < 8; m++) {
            int n = g * 8 + m;
            const float* e = (n < N_ENT) ? (ent + (size_t)n * 64)
                                         : (usr + (size_t)(n - N_ENT) * 64);
            ((float2*)myin)[m * 32 + lane] = ((const float2*)e)[lane];
        }
        __syncwarp();

#pragma unroll
        for (int pp = 0; pp < 2; pp++) {
            ull accA[8], accB[8];
#pragma unroll
            for (int m = 0; m < 8; m++) { accA[m] = 0ull; accB[m] = 0ull; }
#pragma unroll 4
            for (int k2p = 0; k2p < 16; k2p++) {
                ull w00 = sW0u[(2 * k2p) * 128 + lane + 64 * pp];
                ull w01 = sW0u[(2 * k2p) * 128 + lane + 32 + 64 * pp];
                ull w10 = sW0u[(2 * k2p + 1) * 128 + lane + 64 * pp];
                ull w11 = sW0u[(2 * k2p + 1) * 128 + lane + 32 + 64 * pp];
#pragma unroll
                for (int m = 0; m < 8; m++) {
                    ulonglong2 bb = mqI[m * 16 + k2p];
                    FFMA2(accA[m], bb.x, w00);
                    FFMA2(accB[m], bb.x, w01);
                    FFMA2(accA[m], bb.y, w10);
                    FFMA2(accB[m], bb.y, w11);
                }
            }
#pragma unroll
            for (int m = 0; m < 8; m++) {
                mystg[m * 128 + lane + 64 * pp]      = fmaxf(f2sum(accA[m]) + bb0[2 * pp], 0.f);
                mystg[m * 128 + lane + 64 * pp + 32] = fmaxf(f2sum(accB[m]) + bb0[2 * pp + 1], 0.f);
            }
        }
        __syncwarp();

        ull a2[8];
#pragma unroll
        for (int m = 0; m < 8; m++) a2[m] = 0ull;
#pragma unroll 8
        for (int k2p = 0; k2p < 32; k2p++) {
            ulonglong2 w = sW1q[k2p * 32 + lane];
#pragma unroll
            for (int m = 0; m < 8; m++) {
                ulonglong2 bb = mqH[m * 32 + k2p];
                FFMA2(a2[m], bb.x, w.x);
                FFMA2(a2[m], bb.y, w.y);
            }
        }
        float vres[8];
#pragma unroll
        for (int m = 0; m < 8; m++) vres[m] = f2sum(a2[m]) + bb1;
        __syncwarp();
#pragma unroll
        for (int m = 0; m < 8; m++) {
            int node = g * 8 + m;
            g_encoded[(size_t)node * 32 + lane] = vres[m];
            g_ench[(size_t)node * 32 + lane]    = __float2half_rn(vres[m]);
            mystg[m * 32 + lane] = vres[m];
        }
        __syncwarp();

        ull ga[8];
#pragma unroll
        for (int m = 0; m < 8; m++) ga[m] = 0ull;
#pragma unroll
        for (int k2p = 0; k2p < 8; k2p++) {
            ull w0 = sGu[(2 * k2p) * 32 + lane];
            ull w1 = sGu[(2 * k2p + 1) * 32 + lane];
#pragma unroll
            for (int m = 0; m < 8; m++) {
                ulonglong2 bb = mqH[m * 8 + k2p];
                FFMA2(ga[m], bb.x, w0);
                FFMA2(ga[m], bb.y, w1);
            }
        }
#pragma unroll
        for (int m = 0; m < 8; m++) {
            int node = g * 8 + m;
            float gv = f2sum(ga[m]);
            if (lane < 16) g_gd[node * 16 + rr] = gv;
            else           g_gs[node * 16 + rr] = gv;
        }
        __syncwarp();
    }
}

// ---------------- decode ([32]->relu[128]->[64]) + sq-err loss (side stream) -----
__global__ void __launch_bounds__(256, 3) decode_kernel(
    const float* __restrict__ ent, const float* __restrict__ usr,
    const float* __restrict__ W0, const float* __restrict__ b0,
    const float* __restrict__ W1, const float* __restrict__ b1) {
    float2* sW0 = (float2*)dynsmem;
    float2* sW1 = sW0 + 16 * 128;
    float*  stg = (float*)(sW1 + 64 * 64);

    for (int i = threadIdx.x; i < 16 * 128; i += 256) {
        int k2 = i >> 7, j = i & 127;
        sW0[i] = make_float2(W0[(2 * k2) * 128 + j], W0[(2 * k2 + 1) * 128 + j]);
    }
    for (int i = threadIdx.x; i < 64 * 64; i += 256) {
        int k2 = i >> 6, j = i & 63;
        sW1[i] = make_float2(W1[(2 * k2) * 64 + j], W1[(2 * k2 + 1) * 64 + j]);
    }
    __syncthreads();

    const ull* sW0u = (const ull*)sW0;
    const ull* sW1u = (const ull*)sW1;
    const int lane  = threadIdx.x & 31;
    float* mystg    = stg + (threadIdx.x >> 5) * 512;
    ull*   mystgU   = (ull*)mystg;

    const int wid   = (blockIdx.x * 256 + threadIdx.x) >> 5;
    const int nwarp = (gridDim.x * 256) >> 5;

    float bb0[4];
#pragma unroll
    for (int p = 0; p < 4; p++) bb0[p] = b0[lane + 32 * p];
    const float bb1a = b1[lane], bb1b = b1[lane + 32];

    float lsum = 0.f;
    for (int g = wid; g < NND / 4; g += nwarp) {
#pragma unroll
        for (int m = 0; m < 4; m++)
            mystg[m * 32 + lane] = g_encoded[(size_t)(g * 4 + m) * 32 + lane];
        __syncwarp();

        ull acc[4][4];
#pragma unroll
        for (int m = 0; m < 4; m++)
#pragma unroll
            for (int p = 0; p < 4; p++) acc[m][p] = 0ull;
#pragma unroll
        for (int k2 = 0; k2 < 16; k2++) {
            ull w0 = sW0u[k2 * 128 + lane];
            ull w1 = sW0u[k2 * 128 + lane + 32];
            ull w2 = sW0u[k2 * 128 + lane + 64];
            ull w3 = sW0u[k2 * 128 + lane + 96];
#pragma unroll
            for (int m = 0; m < 4; m++) {
                ull b = mystgU[m * 16 + k2];
                FFMA2(acc[m][0], b, w0);
                FFMA2(acc[m][1], b, w1);
                FFMA2(acc[m][2], b, w2);
                FFMA2(acc[m][3], b, w3);
            }
        }
        __syncwarp();
#pragma unroll
        for (int m = 0; m < 4; m++)
#pragma unroll
            for (int p = 0; p < 4; p++)
                mystg[m * 128 + lane + 32 * p] = fmaxf(f2sum(acc[m][p]) + bb0[p], 0.f);
        __syncwarp();

        ull a0[4] = {0ull, 0ull, 0ull, 0ull};
        ull a1[4] = {0ull, 0ull, 0ull, 0ull};
#pragma unroll 8
        for (int k2 = 0; k2 < 64; k2++) {
            ull w0 = sW1u[k2 * 64 + lane];
            ull w1 = sW1u[k2 * 64 + lane + 32];
#pragma unroll
            for (int m = 0; m < 4; m++) {
                ull b = mystgU[m * 64 + k2];
                FFMA2(a0[m], b, w0);
                FFMA2(a1[m], b, w1);
            }
        }
#pragma unroll
        for (int m = 0; m < 4; m++) {
            int n = g * 4 + m;
            const float* e = (n < N_ENT) ? (ent + (size_t)n * 64)
                                         : (usr + (size_t)(n - N_ENT) * 64);
            float q0 = (f2sum(a0[m]) + bb1a) - e[lane];
            float q1 = (f2sum(a1[m]) + bb1b) - e[lane + 32];
            lsum += q0 * q0 + q1 * q1;
        }
        __syncwarp();
    }
#pragma unroll
    for (int o = 16; o; o >>= 1) lsum += __shfl_xor_sync(0xffffffffu, lsum, o);
    if (lane == 0) atomicAdd(&g_loss, lsum);
}

// ---------------- edge scatter: 4 lanes/edge, f16x2 vector reductions ------------
template <int LAYER>
__global__ void __launch_bounds__(256) edge_kernel() {
    const __half* xh = (LAYER == 1) ? g_ench : g_x1h;
    __half* agg      = (LAYER == 1) ? g_agg1h : g_agg2h;

    const int lane = threadIdx.x & 31;
    const int g    = lane >> 2;
    const int sub  = lane & 3;
    const int e8   = ((blockIdx.x * 256 + threadIdx.x) >> 5) * 8;   // < NEDGE, fits int

    float gate = 0.f; int s = 0, d = 0;
    if (lane < 8) {
        ull p = g_epack[e8 + lane];
        s = (int)(p & 0xFFFF);
        d = (int)((p >> 16) & 0xFFFF);
        int r = (int)(p >> 32);
        gate = sigmoidf_(g_gd[d * 16 + r] + g_gs[s * 16 + r]);
    }
    gate = __shfl_sync(0xffffffffu, gate, g);
    s    = __shfl_sync(0xffffffffu, s, g);
    d    = __shfl_sync(0xffffffffu, d, g);

    const uint4 raw = *reinterpret_cast<const uint4*>(xh + (size_t)s * 32 + sub * 8);
    __half2 g2 = __float2half2_rn(gate);
    __half2 h0 = __hmul2(*reinterpret_cast<const __half2*>(&raw.x), g2);
    __half2 h1 = __hmul2(*reinterpret_cast<const __half2*>(&raw.y), g2);
    __half2 h2 = __hmul2(*reinterpret_cast<const __half2*>(&raw.z), g2);
    __half2 h3 = __hmul2(*reinterpret_cast<const __half2*>(&raw.w), g2);

    __half* a = agg + (size_t)d * 32 + sub * 8;
    asm volatile("red.global.add.noftz.v4.f16x2 [%0], {%1, %2, %3, %4};"
                 :: "l"(a),
                    "r"(*reinterpret_cast<unsigned*>(&h0)),
                    "r"(*reinterpret_cast<unsigned*>(&h1)),
                    "r"(*reinterpret_cast<unsigned*>(&h2)),
                    "r"(*reinterpret_cast<unsigned*>(&h3))
                 : "memory");
}

// ---------------- combine v6 (proven R15): NB=8 per warp -------------------------
template <int LAYER>
__global__ void __launch_bounds__(256) combine_kernel(const float* __restrict__ linW,
                                                      const float* __restrict__ linb) {
    constexpr int OUT = (LAYER == 1) ? 32 : 16;
    const float* x    = (LAYER == 1) ? g_encoded : g_x1;
    const __half* agg = (LAYER == 1) ? g_agg1h : g_agg2h;
    float* xo         = (LAYER == 1) ? g_x1 : g_x2;

    __shared__ float2 sW[32 * OUT];
    __shared__ float2 sG[16 * 32];
    __shared__ __align__(16) float stg[8][512];

    for (int i = threadIdx.x; i < 32 * OUT; i += 256) {
        int k2 = i / OUT, j = i % OUT;
        sW[i] = make_float2(linW[(2 * k2) * OUT + j], linW[(2 * k2 + 1) * OUT + j]);
    }
    if (LAYER == 1) {
        for (int i = threadIdx.x; i < 16 * 32; i += 256) {
            int k2 = i >> 5, ln = i & 31;
            int base = (ln & 15) * 64 + ((ln >= 16) ? 32 : 0);
            sG[i] = make_float2(g_wsum2[base + 2 * k2], g_wsum2[base + 2 * k2 + 1]);
        }
    }
    __syncthreads();

    const ull* sWu = (const ull*)sW;
    const ull* sGu = (const ull*)sG;
    const int lane = threadIdx.x & 31;
    const int warp = threadIdx.x >> 5;
    float* mystg   = stg[warp];

    const int base = (blockIdx.x * 8 + warp) * 8;   // 8 nodes per warp; grid=938
    const int j = lane & (OUT - 1);

#pragma unroll
    for (int m = 0; m < 8; m++) {
        int node = base + m;
        float xv = 0.f, av = 0.f;
        if (node < NND) {
            xv = x[(size_t)node * 32 + lane];
            int c = g_cnt[node];
            av = (c > 0) ? __half2float(agg[(size_t)node * 32 + lane]) / (float)c : 0.f;
        }
        mystg[m * 64 + lane]      = xv;
        mystg[m * 64 + 32 + lane] = av;
    }
    __syncwarp();

    ull acc[8];
#pragma unroll
    for (int m = 0; m < 8; m++) acc[m] = 0ull;
    const ulonglong2* mq = (const ulonglong2*)mystg;
#pragma unroll 4
    for (int k2p = 0; k2p < 16; k2p++) {
        ull w0 = sWu[(2 * k2p) * OUT + j];
        ull w1 = sWu[(2 * k2p + 1) * OUT + j];
#pragma unroll
        for (int m = 0; m < 8; m++) {
            ulonglong2 bb = mq[m * 16 + k2p];
            FFMA2(acc[m], bb.x, w0);
            FFMA2(acc[m], bb.y, w1);
        }
    }
    float bias = linb[j];
    float res[8];
#pragma unroll
    for (int m = 0; m < 8; m++) {
        float a = f2sum(acc[m]) + bias;
        res[m] = (a > 0.f) ? a : 0.01f * a;
    }
#pragma unroll
    for (int m = 0; m < 8; m++) {
        int node = base + m;
        if (node < NND && lane < OUT) xo[(size_t)node * OUT + lane] = res[m];
    }

    if (LAYER == 1) {
        __syncwarp();
#pragma unroll
        for (int m = 0; m < 8; m++) {
            int node = base + m;
            if (node < NND) g_x1h[(size_t)node * 32 + lane] = __float2half_rn(res[m]);
            mystg[m * 32 + lane] = res[m];
        }
        __syncwarp();
        int rr = lane & 15;
        ull ga[8];
#pragma unroll
        for (int m = 0; m < 8; m++) ga[m] = 0ull;
#pragma unroll
        for (int k2p = 0; k2p < 8; k2p++) {
            ull w0 = sGu[(2 * k2p) * 32 + lane];
            ull w1 = sGu[(2 * k2p + 1) * 32 + lane];
#pragma unroll
            for (int m = 0; m < 8; m++) {
                ulonglong2 bb = mq[m * 8 + k2p];
                FFMA2(ga[m], bb.x, w0);
                FFMA2(ga[m], bb.y, w1);
            }
        }
#pragma unroll
        for (int m = 0; m < 8; m++) {
            int node = base + m;
            if (node < NND) {
                float gv = f2sum(ga[m]);
                if (lane < 16) g_gd[node * 16 + rr] = gv;
                else           g_gs[node * 16 + rr] = gv;
            }
        }
    }
}

// ---------------- scoring + finalize (merged, as in R13) -------------------------
__global__ void __launch_bounds__(256) score_finalize_kernel(
    const int* __restrict__ users, const int* __restrict__ items,
    float* __restrict__ out, int out_size) {
    if (blockIdx.x == 0 && threadIdx.x == 0) {
        if (out_size > BATCH) out[BATCH] = g_loss * (1.0f / (float)(NND * 64));
        g_loss = 0.f;
    }
    int wid = (blockIdx.x * 256 + threadIdx.x) >> 5;
    if (wid >= BATCH) return;
    int lane = threadIdx.x & 31;
    int un = N_ENT + users[wid];
    int it = items[wid];
    float s = g_x1[(size_t)un * 32 + lane] * g_x1[(size_t)it * 32 + lane];
    if (lane < 16) s += g_x2[(size_t)un * 16 + lane] * g_x2[(size_t)it * 16 + lane];
#pragma unroll
    for (int o = 16; o; o >>= 1) s += __shfl_xor_sync(0xffffffffu, s, o);
    if (lane == 0) out[wid] = s;
}

// ---------------- overlapped resets (R13) -----------------------------------------
__global__ void __launch_bounds__(256) reset_agg1_kernel() {
    int i  = blockIdx.x * blockDim.x + threadIdx.x;
    int st = gridDim.x * blockDim.x;
    unsigned* p = (unsigned*)g_agg1h;
    for (int k = i; k < NND * 16; k += st) p[k] = 0u;
}
__global__ void __launch_bounds__(256) reset_tail_kernel() {
    int i  = blockIdx.x * blockDim.x + threadIdx.x;
    int st = gridDim.x * blockDim.x;
    unsigned* p = (unsigned*)g_agg2h;
    for (int k = i; k < NND * 16; k += st) p[k] = 0u;
    for (int k = i; k < NND; k += st) g_cnt[k] = 0;
}

// ---------------- host launcher (R13 structure; fork/join; capture-legal) --------
extern "C" void kernel_launch(void* const* d_in, const int* in_sizes, int n_in,
                              void* d_out, int out_size) {
    int iu = 0, ii = 1, ies = 2, ied = 3, ier = 4, ient = 5, iusr = 6;
    int ie0 = 7, ib0 = 8, ie1 = 9, ib1 = 10, id0 = 11, idb0 = 12, id1 = 13, idb1 = 14;
    int iWr1 = 15, ilW1 = 16, ilb1 = 17, iWr2 = 18, ilW2 = 19, ilb2 = 20;
    bool dict_order = (n_in >= 21 && in_sizes[0] == BATCH && in_sizes[2] == NEDGE &&
                       in_sizes[5] == N_ENT * 64);
    if (!dict_order) {
        ient = 0; iusr = 1; ie0 = 2; ib0 = 3; ie1 = 4; ib1 = 5;
        id0 = 6; idb0 = 7; id1 = 8; idb1 = 9;
        iWr1 = 10; ilW1 = 11; ilb1 = 12; iWr2 = 13; ilW2 = 14; ilb2 = 15;
        iu = 16; ii = 17; ies = 18; ied = 19; ier = 20;
    }
    const int* users = (const int*)d_in[iu];
    const int* items = (const int*)d_in[ii];
    const int* esrc  = (const int*)d_in[ies];
    const int* edst  = (const int*)d_in[ied];
    const int* erel  = (const int*)d_in[ier];
    const float* ent = (const float*)d_in[ient];
    const float* usr = (const float*)d_in[iusr];
    float* out = (float*)d_out;

    static cudaStream_t sPrep = nullptr, sDec = nullptr;
    static cudaEvent_t  eRoot = nullptr, ePrep = nullptr, eEnc = nullptr,
                        eDec = nullptr, eC1 = nullptr, eC2 = nullptr, eRst = nullptr;
    if (!sPrep) {
        cudaStreamCreateWithFlags(&sPrep, cudaStreamNonBlocking);
        cudaStreamCreateWithFlags(&sDec, cudaStreamNonBlocking);
        cudaEventCreateWithFlags(&eRoot, cudaEventDisableTiming);
        cudaEventCreateWithFlags(&ePrep, cudaEventDisableTiming);
        cudaEventCreateWithFlags(&eEnc,  cudaEventDisableTiming);
        cudaEventCreateWithFlags(&eDec,  cudaEventDisableTiming);
        cudaEventCreateWithFlags(&eC1,   cudaEventDisableTiming);
        cudaEventCreateWithFlags(&eC2,   cudaEventDisableTiming);
        cudaEventCreateWithFlags(&eRst,  cudaEventDisableTiming);
        cudaFuncSetAttribute(encode_kernel, cudaFuncAttributeMaxDynamicSharedMemorySize, 102400);
        cudaFuncSetAttribute(decode_kernel, cudaFuncAttributeMaxDynamicSharedMemorySize, 65536);
    }

    cudaEventRecord(eRoot, 0);

    // launch 1 (main): wsum layer-1 (encode needs it)
    wsum_a_kernel<<<4, 256>>>((const float*)d_in[iWr1]);

    // launch 2 (side): pack + count, overlapped with encode
    cudaStreamWaitEvent(sPrep, eRoot, 0);
    prep_kernel<<<(NEDGE + 255) / 256, 256, 0, sPrep>>>(esrc, edst, erel);
    cudaEventRecord(ePrep, sPrep);

    // launch 3 (main): wsum layer-2
    wsum_b_kernel<<<4, 256>>>((const float*)d_in[iWr2]);

    // launch 4 (main, PROFILED): encode v4
    encode_kernel<<<296, 256, 102400>>>(ent, usr,
                                (const float*)d_in[ie0], (const float*)d_in[ib0],
                                (const float*)d_in[ie1], (const float*)d_in[ib1]);
    cudaEventRecord(eEnc, 0);

    // edge layer 1 — after prep joins
    cudaStreamWaitEvent(0, ePrep, 0);
    edge_kernel<1><<<NEDGE / 64, 256>>>();

    // side: decode/loss overlapped with edge1/combine1/edge2
    cudaStreamWaitEvent(sDec, eEnc, 0);
    decode_kernel<<<444, 256, 65536, sDec>>>(ent, usr,
                                (const float*)d_in[id0], (const float*)d_in[idb0],
                                (const float*)d_in[id1], (const float*)d_in[idb1]);
    cudaEventRecord(eDec, sDec);

    // combine 1 v6 (NB=8; grid ceil(NND/64)=938)
    combine_kernel<1><<<938, 256>>>((const float*)d_in[ilW1],
                                    (const float*)d_in[ilb1]);
    cudaEventRecord(eC1, 0);

    // side: reset agg1 under edge2
    cudaStreamWaitEvent(sPrep, eC1, 0);
    reset_agg1_kernel<<<960, 256, 0, sPrep>>>();

    // layer 2
    edge_kernel<2><<<NEDGE / 64, 256>>>();
    combine_kernel<2><<<938, 256>>>((const float*)d_in[ilW2],
                                    (const float*)d_in[ilb2]);
    cudaEventRecord(eC2, 0);

    // side: reset agg2 + cnt
    cudaStreamWaitEvent(sPrep, eC2, 0);
    reset_tail_kernel<<<960, 256, 0, sPrep>>>();
    cudaEventRecord(eRst, sPrep);

    // scoring + finalize (joins decode + resets)
    cudaStreamWaitEvent(0, eDec, 0);
    cudaStreamWaitEvent(0, eRst, 0);
    score_finalize_kernel<<<(BATCH * 32 + 255) / 256, 256>>>(users, items, out, out_size);
}